// round 4
// baseline (speedup 1.0000x reference)
#include <cuda_runtime.h>
#include <math.h>

#define FD   128
#define EMAX 200000
#define NMAX 8000
#define AMAX 400000
#define GMAX 128
#define PI_F 3.14159265358979323846f

// ------------------------- scratch (device globals; no allocs) -------------
__device__ float g_e   [(size_t)EMAX * FD];   // edge features e
__device__ float g_agg [(size_t)EMAX * FD];   // per-block angle aggregation
__device__ float g_ef0 [(size_t)EMAX * 5];    // rbf features (incl sqrt(2/5))
__device__ float g_v   [(size_t)NMAX * FD];   // atom features
__device__ float g_gate[(size_t)NMAX * FD];   // sigmoid(v@Wg+bg) per atom
__device__ float g_pi  [(size_t)NMAX * FD];   // v @ We1[0:128]
__device__ float g_pj  [(size_t)NMAX * FD];   // v @ We1[128:256]
__device__ float g_pai [(size_t)NMAX * FD];   // v @ Wa1[0:128]
__device__ float g_paj [(size_t)NMAX * FD];   // v @ Wa1[128:256]
__device__ float g_angf[(size_t)AMAX * 16];   // rad x P x fc^2
__device__ int   g_iij [AMAX];
__device__ int   g_kat [AMAX];
__device__ int   g_boff[GMAX];
__device__ int   g_acum[GMAX + 1];

// ------------------------- helpers ----------------------------------------
__device__ __forceinline__ void fma4(float4& a, float s, float4 b){
    a.x = fmaf(s, b.x, a.x);
    a.y = fmaf(s, b.y, a.y);
    a.z = fmaf(s, b.z, a.z);
    a.w = fmaf(s, b.w, a.w);
}

__device__ __forceinline__ float sigmf(float x){ return __fdividef(1.0f, 1.0f + __expf(-x)); }
__device__ __forceinline__ float swishf(float x){ return x * sigmf(x); }
__device__ __forceinline__ float4 swish4(float4 a){
    return make_float4(swishf(a.x), swishf(a.y), swishf(a.z), swishf(a.w));
}
__device__ __forceinline__ float4 sigm4(float4 a){
    return make_float4(sigmf(a.x), sigmf(a.y), sigmf(a.z), sigmf(a.w));
}
__device__ __forceinline__ float4 add4(float4 a, float4 b){
    return make_float4(a.x+b.x, a.y+b.y, a.z+b.z, a.w+b.w);
}
__device__ __forceinline__ float4 mul4(float4 a, float4 b){
    return make_float4(a.x*b.x, a.y*b.y, a.z*b.z, a.w*b.w);
}
__device__ __forceinline__ void red4(float* p, float4 v){
    asm volatile("red.global.add.v4.f32 [%0], {%1,%2,%3,%4};"
                 :: "l"(p), "f"(v.x), "f"(v.y), "f"(v.z), "f"(v.w) : "memory");
}

// ------------------------- prep kernels ------------------------------------
__global__ void k_offsets(const int* __restrict__ tnb, const int* __restrict__ tna, int G){
    if (threadIdx.x == 0 && blockIdx.x == 0){
        int ob = 0, oa = 0;
        g_acum[0] = 0;
        for (int g = 0; g < G; g++){
            g_boff[g] = ob;
            ob += tnb[g];
            oa += tna[g];
            g_acum[g + 1] = oa;
        }
    }
}

__global__ void k_angle_pre(const int* __restrict__ tbi,
                            const float* __restrict__ norm_ik,
                            const float* __restrict__ cosang,
                            const int* __restrict__ edge_index,
                            int A, int E, int G)
{
    int a = blockIdx.x * blockDim.x + threadIdx.x;
    if (a >= A) return;
    // find graph: largest g with g_acum[g] <= a
    int lo = 0, hi = G - 1;
    while (lo < hi){ int mid = (lo + hi + 1) >> 1; if (g_acum[mid] <= a) lo = mid; else hi = mid - 1; }
    int off = g_boff[lo];
    int iij = tbi[2*a]     + off;
    int iik = tbi[2*a + 1] + off;
    g_iij[a] = iij;
    g_kat[a] = edge_index[E + iik];         // recv[idx_ik]

    float r = norm_ik[a];
    float c = cosang[a];
    float x = r * 0.25f;                    // r / CUT3
    float x2 = x*x, x3 = x2*x;
    float fc = 1.0f - 6.0f*x3*x2 + 15.0f*x2*x2 - 10.0f*x3;
    float invr = 1.0f / r;
    float s2 = fc * fc * invr;              // fold 1/r + fc^2 (one fc from shrb, one from msg)
    float rad[4];
    #pragma unroll
    for (int n = 0; n < 4; n++) rad[n] = sinf((float)(n+1) * PI_F * x) * s2;
    float P0 = 1.0f, P1 = c;
    float P2 = 0.5f * (3.0f*c*c - 1.0f);
    float P3 = 0.5f * c * (5.0f*c*c - 3.0f);
    #pragma unroll
    for (int n = 0; n < 4; n++)
        *(float4*)&g_angf[(size_t)a*16 + n*4] = make_float4(rad[n]*P0, rad[n]*P1, rad[n]*P2, rad[n]*P3);
}

__global__ void k_edge_init(const float* __restrict__ edge_dist,
                            const float* __restrict__ W_enc,
                            const float* __restrict__ b_enc, int E)
{
    int gw   = (blockIdx.x * blockDim.x + threadIdx.x) >> 5;
    int lane = threadIdx.x & 31;
    if (gw >= E) return;
    float r    = edge_dist[gw];
    float invr = 1.0f / r;
    const float C = sqrtf(2.0f / 5.0f);
    float ef[5];
    #pragma unroll
    for (int n = 0; n < 5; n++) ef[n] = C * sinf((float)(n+1) * PI_F * r * 0.2f) * invr;
    if (lane < 5) g_ef0[(size_t)gw*5 + lane] = ef[lane];
    int fo = lane * 4;
    float4 acc = *(const float4*)&b_enc[fo];
    #pragma unroll
    for (int n = 0; n < 5; n++){
        float4 w = *(const float4*)&W_enc[n*FD + fo];
        fma4(acc, ef[n], w);
    }
    *(float4*)&g_e[(size_t)gw*FD + fo] = swish4(acc);
}

__global__ void k_vinit(const int* __restrict__ z, const float* __restrict__ emb, int N){
    int t = blockIdx.x * blockDim.x + threadIdx.x;
    if (t >= N * 32) return;
    int n = t >> 5, fo = (t & 31) * 4;
    *(float4*)&g_v[(size_t)n*FD + fo] = *(const float4*)&emb[(size_t)z[n]*FD + fo];
}

// ------------------- per-block: atom precompute (gate + concat parts) -------
__global__ __launch_bounds__(256)
void k_gate_pre(const float* __restrict__ Wg,  const float* __restrict__ bg,
                const float* __restrict__ We1b, const float* __restrict__ Wa1b, int N)
{
    __shared__ float sv[8][FD];
    const int warp = threadIdx.x >> 5, lane = threadIdx.x & 31;
    const int fo = lane * 4;
    for (int base = blockIdx.x * 8; base < N; base += gridDim.x * 8){
        int na = N - base; if (na > 8) na = 8;
        __syncthreads();
        for (int idx = threadIdx.x; idx < na * 32; idx += blockDim.x){
            int rr = idx >> 5, cc = (idx & 31) * 4;
            *(float4*)&sv[rr][cc] = *(const float4*)&g_v[(size_t)(base+rr)*FD + cc];
        }
        __syncthreads();
        if (warp < 5){
            const float* W = (warp == 0) ? Wg
                           : (warp == 1) ? We1b
                           : (warp == 2) ? (We1b + FD*FD)
                           : (warp == 3) ? Wa1b
                           :               (Wa1b + FD*FD);
            float4 acc[8];
            #pragma unroll
            for (int j = 0; j < 8; j++) acc[j] = make_float4(0,0,0,0);
            #pragma unroll 4
            for (int k4 = 0; k4 < 32; k4++){
                float4 w0 = *(const float4*)&W[(k4*4+0)*FD + fo];
                float4 w1 = *(const float4*)&W[(k4*4+1)*FD + fo];
                float4 w2 = *(const float4*)&W[(k4*4+2)*FD + fo];
                float4 w3 = *(const float4*)&W[(k4*4+3)*FD + fo];
                #pragma unroll
                for (int j = 0; j < 8; j++){
                    float4 s = *(const float4*)&sv[j][k4*4];
                    fma4(acc[j], s.x, w0); fma4(acc[j], s.y, w1);
                    fma4(acc[j], s.z, w2); fma4(acc[j], s.w, w3);
                }
            }
            if (warp == 0){
                float4 b4 = *(const float4*)&bg[fo];
                for (int j = 0; j < na; j++)
                    *(float4*)&g_gate[(size_t)(base+j)*FD + fo] = sigm4(add4(acc[j], b4));
            } else {
                float* dst = (warp == 1) ? g_pi : (warp == 2) ? g_pj : (warp == 3) ? g_pai : g_paj;
                for (int j = 0; j < na; j++)
                    *(float4*)&dst[(size_t)(base+j)*FD + fo] = acc[j];
            }
        }
    }
}

// ------------------- per-block: angle message scatter -----------------------
__global__ __launch_bounds__(256)
void k_angle(const float* __restrict__ Wang, int A)
{
    __shared__ float sW[16 * FD];
    for (int i = threadIdx.x; i < 16*FD/4; i += blockDim.x)
        ((float4*)sW)[i] = ((const float4*)Wang)[i];
    __syncthreads();
    const int lane = threadIdx.x & 31;
    const int fo = lane * 4;
    int gw = (blockIdx.x * blockDim.x + threadIdx.x) >> 5;
    int nw = (gridDim.x * blockDim.x) >> 5;
    for (int a = gw; a < A; a += nw){
        int iij = g_iij[a], kat = g_kat[a];
        const float4* af = (const float4*)&g_angf[(size_t)a*16];
        float4 acc = make_float4(0,0,0,0);
        #pragma unroll
        for (int k4 = 0; k4 < 4; k4++){
            float4 s  = af[k4];
            float4 w0 = *(const float4*)&sW[(k4*4+0)*FD + fo];
            float4 w1 = *(const float4*)&sW[(k4*4+1)*FD + fo];
            float4 w2 = *(const float4*)&sW[(k4*4+2)*FD + fo];
            float4 w3 = *(const float4*)&sW[(k4*4+3)*FD + fo];
            fma4(acc, s.x, w0); fma4(acc, s.y, w1); fma4(acc, s.z, w2); fma4(acc, s.w, w3);
        }
        float4 g = *(const float4*)&g_gate[(size_t)kat*FD + fo];
        red4(&g_agg[(size_t)iij*FD + fo], mul4(acc, g));
    }
}

// ------------------- per-block: fused edge update ---------------------------
// smem: 3x(128x128) W + 2x(5x128) + 3x128 bias + 8 warps x 4 edges x 128 stage
#define SMEM_EDGE_FLOATS (3*FD*FD + 2*5*FD + 3*FD + 8*4*FD)

__device__ __forceinline__ void matvec128(const float* __restrict__ sW,
                                          const float* __restrict__ myst,
                                          int fo, float4 acc[4])
{
    #pragma unroll 4
    for (int k4 = 0; k4 < 32; k4++){
        float4 w0 = *(const float4*)&sW[(k4*4+0)*FD + fo];
        float4 w1 = *(const float4*)&sW[(k4*4+1)*FD + fo];
        float4 w2 = *(const float4*)&sW[(k4*4+2)*FD + fo];
        float4 w3 = *(const float4*)&sW[(k4*4+3)*FD + fo];
        #pragma unroll
        for (int j = 0; j < 4; j++){
            float4 s = *(const float4*)&myst[j*FD + k4*4];
            fma4(acc[j], s.x, w0); fma4(acc[j], s.y, w1);
            fma4(acc[j], s.z, w2); fma4(acc[j], s.w, w3);
        }
    }
}

__global__ __launch_bounds__(256, 1)
void k_edge_fused(const float* __restrict__ Wtb,  const float* __restrict__ btb,
                  const float* __restrict__ We1e, const float* __restrict__ be1,
                  const float* __restrict__ We0,
                  const float* __restrict__ Wa1e, const float* __restrict__ ba1,
                  const float* __restrict__ Wa0,
                  const int* __restrict__ edge_index, int E)
{
    extern __shared__ float sm[];
    float* sWtb = sm;
    float* sWe1 = sm + FD*FD;
    float* sWa1 = sm + 2*FD*FD;
    float* sWe0 = sm + 3*FD*FD;
    float* sWa0 = sWe0 + 5*FD;
    float* sbtb = sWa0 + 5*FD;
    float* sbe1 = sbtb + FD;
    float* sba1 = sbe1 + FD;
    float* stg  = sba1 + FD;

    for (int i = threadIdx.x; i < FD*FD/4; i += blockDim.x){
        ((float4*)sWtb)[i] = ((const float4*)Wtb )[i];
        ((float4*)sWe1)[i] = ((const float4*)We1e)[i];
        ((float4*)sWa1)[i] = ((const float4*)Wa1e)[i];
    }
    for (int i = threadIdx.x; i < 5*FD/4; i += blockDim.x){
        ((float4*)sWe0)[i] = ((const float4*)We0)[i];
        ((float4*)sWa0)[i] = ((const float4*)Wa0)[i];
    }
    if (threadIdx.x < FD){
        sbtb[threadIdx.x] = btb[threadIdx.x];
        sbe1[threadIdx.x] = be1[threadIdx.x];
        sba1[threadIdx.x] = ba1[threadIdx.x];
    }
    __syncthreads();

    const int warp = threadIdx.x >> 5;
    const int lane = threadIdx.x & 31;
    const int fo = lane * 4;
    float* myst = stg + warp * 4 * FD;

    for (int base0 = blockIdx.x * 32; base0 < E; base0 += gridDim.x * 32){
        const int base = base0 + warp * 4;
        int ne = E - base; if (ne > 4) ne = 4; if (ne < 0) ne = 0;

        int sendi[4], recvi[4];
        float ef[4][5];
        float4 cur[4];    // running e-vector: e_old -> e1 -> e2
        #pragma unroll
        for (int j = 0; j < 4; j++){
            if (j < ne){
                int eid = base + j;
                sendi[j] = edge_index[eid];
                recvi[j] = edge_index[E + eid];
                #pragma unroll
                for (int n = 0; n < 5; n++) ef[j][n] = g_ef0[(size_t)eid*5 + n];
                *(float4*)&myst[j*FD + fo] = *(const float4*)&g_agg[(size_t)eid*FD + fo];
                cur[j] = *(const float4*)&g_e[(size_t)eid*FD + fo];
            } else {
                sendi[j] = 0; recvi[j] = 0;
                #pragma unroll
                for (int n = 0; n < 5; n++) ef[j][n] = 0.0f;
                cur[j] = make_float4(0,0,0,0);
                *(float4*)&myst[j*FD + fo] = make_float4(0,0,0,0);
            }
        }
        __syncwarp();

        // ---- stage 1: e1 = e + swish(agg @ Wtb + btb)
        float4 acc[4];
        {
            float4 b4 = *(const float4*)&sbtb[fo];
            #pragma unroll
            for (int j = 0; j < 4; j++) acc[j] = b4;
        }
        matvec128(sWtb, myst, fo, acc);
        #pragma unroll
        for (int j = 0; j < 4; j++) cur[j] = add4(cur[j], swish4(acc[j]));
        __syncwarp();
        #pragma unroll
        for (int j = 0; j < 4; j++) *(float4*)&myst[j*FD + fo] = cur[j];
        __syncwarp();

        // ---- stage 2: e2 = e1 + swish(pi[s] + pj[r] + e1@We1e + be1) * (ef0@We0)
        float4 p0[4];
        #pragma unroll
        for (int j = 0; j < 4; j++) p0[j] = make_float4(0,0,0,0);
        #pragma unroll
        for (int n = 0; n < 5; n++){
            float4 w = *(const float4*)&sWe0[n*FD + fo];
            #pragma unroll
            for (int j = 0; j < 4; j++) fma4(p0[j], ef[j][n], w);
        }
        {
            float4 b4 = *(const float4*)&sbe1[fo];
            #pragma unroll
            for (int j = 0; j < 4; j++){
                float4 a = *(const float4*)&g_pi[(size_t)sendi[j]*FD + fo];
                float4 b = *(const float4*)&g_pj[(size_t)recvi[j]*FD + fo];
                acc[j] = make_float4(b4.x+a.x+b.x, b4.y+a.y+b.y, b4.z+a.z+b.z, b4.w+a.w+b.w);
            }
        }
        matvec128(sWe1, myst, fo, acc);
        #pragma unroll
        for (int j = 0; j < 4; j++) cur[j] = add4(cur[j], mul4(swish4(acc[j]), p0[j]));
        #pragma unroll
        for (int j = 0; j < 4; j++)
            if (j < ne) *(float4*)&g_e[(size_t)(base+j)*FD + fo] = cur[j];
        __syncwarp();
        #pragma unroll
        for (int j = 0; j < 4; j++) *(float4*)&myst[j*FD + fo] = cur[j];
        __syncwarp();

        // ---- stage 3: v[recv] += swish(pai[s] + paj[r] + e2@Wa1e + ba1) * (ef0@Wa0)
        #pragma unroll
        for (int j = 0; j < 4; j++) p0[j] = make_float4(0,0,0,0);
        #pragma unroll
        for (int n = 0; n < 5; n++){
            float4 w = *(const float4*)&sWa0[n*FD + fo];
            #pragma unroll
            for (int j = 0; j < 4; j++) fma4(p0[j], ef[j][n], w);
        }
        {
            float4 b4 = *(const float4*)&sba1[fo];
            #pragma unroll
            for (int j = 0; j < 4; j++){
                float4 a = *(const float4*)&g_pai[(size_t)sendi[j]*FD + fo];
                float4 b = *(const float4*)&g_paj[(size_t)recvi[j]*FD + fo];
                acc[j] = make_float4(b4.x+a.x+b.x, b4.y+a.y+b.y, b4.z+a.z+b.z, b4.w+a.w+b.w);
            }
        }
        matvec128(sWa1, myst, fo, acc);
        #pragma unroll
        for (int j = 0; j < 4; j++){
            if (j < ne){
                float4 m = mul4(swish4(acc[j]), p0[j]);
                red4(&g_v[(size_t)recvi[j]*FD + fo], m);
            }
        }
    }
}

// ------------------- final readout MLP -------------------------------------
__global__ __launch_bounds__(128)
void k_final(const float* __restrict__ W1, const float* __restrict__ b1,
             const float* __restrict__ W2, const float* __restrict__ b2,
             const float* __restrict__ W3, const float* __restrict__ b3,
             float* __restrict__ out, int N)
{
    __shared__ float sv[FD];
    __shared__ float sh[FD];
    __shared__ float sred[4];
    int n = blockIdx.x;
    if (n >= N) return;
    int t = threadIdx.x;
    sv[t] = g_v[(size_t)n*FD + t];
    __syncthreads();
    float acc = b1[t];
    #pragma unroll 8
    for (int k = 0; k < FD; k++) acc = fmaf(sv[k], W1[k*FD + t], acc);
    sh[t] = swishf(acc);
    __syncthreads();
    acc = b2[t];
    #pragma unroll 8
    for (int k = 0; k < FD; k++) acc = fmaf(sh[k], W2[k*FD + t], acc);
    float prod = swishf(acc) * W3[t];
    #pragma unroll
    for (int o = 16; o > 0; o >>= 1) prod += __shfl_down_sync(0xffffffffu, prod, o);
    if ((t & 31) == 0) sred[t >> 5] = prod;
    __syncthreads();
    if (t == 0) out[n] = sred[0] + sred[1] + sred[2] + sred[3] + b3[0];
}

// ------------------------- launch ------------------------------------------
extern "C" void kernel_launch(void* const* d_in, const int* in_sizes, int n_in,
                              void* d_out, int out_size)
{
    const int*   atomic_numbers = (const int*  )d_in[0];
    const int*   edge_index     = (const int*  )d_in[1];
    const float* edge_dist      = (const float*)d_in[2];
    const int*   tbi            = (const int*  )d_in[3];
    const float* norm_ik        = (const float*)d_in[4];
    const float* cos_ang        = (const float*)d_in[5];
    const int*   tnb            = (const int*  )d_in[6];
    const int*   tna            = (const int*  )d_in[7];
    const float* emb            = (const float*)d_in[8];
    const float* W_enc          = (const float*)d_in[9];
    const float* b_enc          = (const float*)d_in[10];
    const float* W_angle        = (const float*)d_in[11];
    const float* Wg             = (const float*)d_in[12];
    const float* bg             = (const float*)d_in[13];
    const float* W_tb           = (const float*)d_in[14];
    const float* b_tb           = (const float*)d_in[15];
    const float* We1            = (const float*)d_in[16];
    const float* be1            = (const float*)d_in[17];
    const float* We0            = (const float*)d_in[18];
    const float* Wa1            = (const float*)d_in[19];
    const float* ba1            = (const float*)d_in[20];
    const float* Wa0            = (const float*)d_in[21];
    const float* W1             = (const float*)d_in[22];
    const float* b1             = (const float*)d_in[23];
    const float* W2             = (const float*)d_in[24];
    const float* b2             = (const float*)d_in[25];
    const float* W3             = (const float*)d_in[26];
    const float* b3             = (const float*)d_in[27];

    const int N = in_sizes[0];           // atoms
    const int E = in_sizes[2];           // edges
    const int A = in_sizes[4];           // angles
    const int G = in_sizes[6];           // graphs
    float* out = (float*)d_out;

    const size_t smem_edge = (size_t)SMEM_EDGE_FLOATS * sizeof(float);
    cudaFuncSetAttribute(k_edge_fused, cudaFuncAttributeMaxDynamicSharedMemorySize, (int)smem_edge);

    float* aggp = nullptr;
    cudaGetSymbolAddress((void**)&aggp, g_agg);

    k_offsets  <<<1, 32>>>(tnb, tna, G);
    k_angle_pre<<<(A + 255) / 256, 256>>>(tbi, norm_ik, cos_ang, edge_index, A, E, G);
    k_edge_init<<<(E + 3) / 4, 128>>>(edge_dist, W_enc, b_enc, E);
    k_vinit    <<<(N * 32 + 255) / 256, 256>>>(atomic_numbers, emb, N);

    for (int b = 0; b < 4; b++){
        cudaMemsetAsync(aggp, 0, (size_t)E * FD * sizeof(float), 0);
        k_gate_pre<<<(N + 7) / 8, 256>>>(Wg + (size_t)b*FD*FD, bg + (size_t)b*FD,
                                         We1 + (size_t)b*3*FD*FD, Wa1 + (size_t)b*3*FD*FD, N);
        k_angle<<<1184, 256>>>(W_angle + (size_t)b*16*FD, A);
        k_edge_fused<<<152, 256, smem_edge>>>(
            W_tb + (size_t)b*FD*FD,            b_tb + (size_t)b*FD,
            We1  + (size_t)b*3*FD*FD + 2*FD*FD, be1 + (size_t)b*FD,
            We0  + (size_t)b*5*FD,
            Wa1  + (size_t)b*3*FD*FD + 2*FD*FD, ba1 + (size_t)b*FD,
            Wa0  + (size_t)b*5*FD,
            edge_index, E);
    }

    k_final<<<N, 128>>>(W1, b1, W2, b2, W3, b3, out, N);
}